// round 14
// baseline (speedup 1.0000x reference)
#include <cuda_runtime.h>
#include <cuda_fp16.h>
#include <math.h>
#include <stdint.h>

#define B    16
#define C    128
#define HH   128
#define WW   128
#define HW   (HH*WW)
#define KK   9
#define KCH  16
#define NCHUNK (C/KCH)     // 8
#define NSTAGE 6

// Scratch. g_midh layout: [b][c][h][w]
__device__ __half g_midh[(size_t)B*C*HW];
__device__ __half g_wh[C*C];               // conv weights fp16 [o][k]
__device__ float  g_att[B*C];              // CA attention
__device__ float  g_t[B*C];                // hidden MLP activations
__device__ float  g_hid[B*16];             // CA hidden activations

__device__ __forceinline__ float lrelu(float v) { return v > 0.f ? v : 0.1f*v; }

__device__ __forceinline__ void cp16(void* dst, const void* src) {
    uint32_t d = (uint32_t)__cvta_generic_to_shared(dst);
    asm volatile("cp.async.cg.shared.global [%0], [%1], 16;" :: "r"(d), "l"(src));
}
__device__ __forceinline__ void cp_commit() {
    asm volatile("cp.async.commit_group;");
}

__device__ __forceinline__ void ldmatrix_x4(uint32_t* r, const void* p) {
    uint32_t a = (uint32_t)__cvta_generic_to_shared(p);
    asm volatile("ldmatrix.sync.aligned.m8n8.x4.shared.b16 {%0,%1,%2,%3}, [%4];"
                 : "=r"(r[0]), "=r"(r[1]), "=r"(r[2]), "=r"(r[3]) : "r"(a));
}
__device__ __forceinline__ void ldmatrix_x2_t(uint32_t* r, const void* p) {
    uint32_t a = (uint32_t)__cvta_generic_to_shared(p);
    asm volatile("ldmatrix.sync.aligned.m8n8.x2.trans.shared.b16 {%0,%1}, [%2];"
                 : "=r"(r[0]), "=r"(r[1]) : "r"(a));
}
__device__ __forceinline__ void mma_f16(float* d, const uint32_t* a, const uint32_t* b) {
    asm volatile(
        "mma.sync.aligned.m16n8k16.row.col.f32.f16.f16.f32 "
        "{%0,%1,%2,%3}, {%4,%5,%6,%7}, {%8,%9}, {%0,%1,%2,%3};"
        : "+f"(d[0]), "+f"(d[1]), "+f"(d[2]), "+f"(d[3])
        : "r"(a[0]), "r"(a[1]), "r"(a[2]), "r"(a[3]), "r"(b[0]), "r"(b[1]));
}

// ---------------------------------------------------------------------------
// P1: one block per MLP output j (144 = 128 t-outputs + 16 CA-hidden).
// ---------------------------------------------------------------------------
__global__ void prep1_kernel(const float* __restrict__ deg,
                             const float* __restrict__ w1,
                             const float* __restrict__ caw1)
{
    const int j    = blockIdx.x;
    const int tid  = threadIdx.x;
    const int wid  = tid >> 5;
    const int lane = tid & 31;

    __shared__ float sdeg[B][C];

    #pragma unroll
    for (int i = tid; i < B*C; i += 256)
        ((float*)sdeg)[i] = deg[i];
    __syncthreads();

    const float* wrow = (j < 128) ? (w1 + j*C) : (caw1 + (j-128)*C);
    float w[4];
    #pragma unroll
    for (int u = 0; u < 4; ++u) w[u] = wrow[lane*4 + u];

    #pragma unroll
    for (int rep = 0; rep < 2; ++rep) {
        const int b = wid + rep*8;
        float acc = 0.f;
        #pragma unroll
        for (int u = 0; u < 4; ++u) acc += sdeg[b][lane*4 + u]*w[u];
        #pragma unroll
        for (int s = 16; s > 0; s >>= 1) acc += __shfl_xor_sync(0xffffffffu, acc, s);
        if (lane == 0) {
            if (j < 128) g_t[b*C + j]        = lrelu(acc);
            else         g_hid[b*16 + j-128] = lrelu(acc);
        }
    }
}

// ---------------------------------------------------------------------------
// P1b: CA attention sigmoid + fp16 weight conversion. grid = B, block = 256.
// ---------------------------------------------------------------------------
__global__ void prep1b_kernel(const float* __restrict__ caw2,
                              const float* __restrict__ convw)
{
    const int b   = blockIdx.x;
    const int tid = threadIdx.x;

    __shared__ float shid[16];
    if (tid < 16) shid[tid] = g_hid[b*16 + tid];
    __syncthreads();

    if (tid < C) {
        float acc = 0.f;
        const float* wrow = caw2 + tid*16;
        #pragma unroll
        for (int r = 0; r < 16; ++r) acc += shid[r]*wrow[r];
        g_att[b*C + tid] = 1.f/(1.f + expf(-acc));
    }

    {
        const int base = b*1024 + tid*4;
        float4 v = *(const float4*)(convw + base);
        g_wh[base+0] = __float2half(v.x);
        g_wh[base+1] = __float2half(v.y);
        g_wh[base+2] = __float2half(v.z);
        g_wh[base+3] = __float2half(v.w);
    }
}

// ---------------------------------------------------------------------------
// dwconv (+ fused coefficient dots): one block per (b,c) plane.
// 16 px/thread row segments: 18 values per row (4xLDG.128 + 2 scalar edges),
// interior neighbors from registers. 2x fewer LSU ops than 4px version.
// grid = B*C, block = 256 (thread -> row=tid>>3 (+32*rr), seg=(tid&7)*16).
// ---------------------------------------------------------------------------
__global__ void dwconv_kernel(const float* __restrict__ x0,
                              const float* __restrict__ w2)
{
    const int bc   = blockIdx.x;
    const int b    = bc >> 7;
    const int c    = bc & 127;
    const int tid  = threadIdx.x;
    const int wid  = tid >> 5;
    const int lane = tid & 31;

    __shared__ float sk[9];
    __shared__ float st[C];

    if (tid < C) st[tid] = g_t[b*C + tid];
    __syncthreads();

    for (int j = wid; j < KK; j += 8) {
        const float* wrow = w2 + (size_t)(c*KK + j)*C;
        float acc = 0.f;
        #pragma unroll
        for (int u = 0; u < 4; ++u) {
            const int idx = lane*4 + u;
            acc += st[idx]*wrow[idx];
        }
        #pragma unroll
        for (int s = 16; s > 0; s >>= 1) acc += __shfl_xor_sync(0xffffffffu, acc, s);
        if (lane == 0) sk[j] = acc;
    }
    __syncthreads();

    float k[9];
    #pragma unroll
    for (int i = 0; i < 9; ++i) k[i] = sk[i];

    const float* __restrict__ src = x0 + (size_t)bc*HW;
    __half* __restrict__ dst = g_midh + (size_t)bc*HW;

    const int row0 = tid >> 3;          // 0..31
    const int seg  = (tid & 7) * 16;    // 0,16,...,112

    #pragma unroll
    for (int rr = 0; rr < 4; ++rr) {
        const int h = row0 + rr*32;

        float v[3][18];
        #pragma unroll
        for (int dr = 0; dr < 3; ++dr) {
            const int hh = h + dr - 1;
            if (hh < 0 || hh >= HH) {
                #pragma unroll
                for (int i = 0; i < 18; ++i) v[dr][i] = 0.f;
            } else {
                const float* row = src + hh*WW + seg;
                #pragma unroll
                for (int q = 0; q < 4; ++q) {
                    float4 t4 = *(const float4*)(row + q*4);
                    v[dr][1 + q*4 + 0] = t4.x;
                    v[dr][1 + q*4 + 1] = t4.y;
                    v[dr][1 + q*4 + 2] = t4.z;
                    v[dr][1 + q*4 + 3] = t4.w;
                }
                v[dr][0]  = (seg > 0)   ? row[-1] : 0.f;
                v[dr][17] = (seg < 112) ? row[16] : 0.f;
            }
        }

        __half2 ov[8];
        #pragma unroll
        for (int i = 0; i < 16; i += 2) {
            float a0 = 0.f, a1 = 0.f;
            #pragma unroll
            for (int dr = 0; dr < 3; ++dr) {
                const float k0 = k[dr*3+0], k1 = k[dr*3+1], k2 = k[dr*3+2];
                a0 += k0*v[dr][i]   + k1*v[dr][i+1] + k2*v[dr][i+2];
                a1 += k0*v[dr][i+1] + k1*v[dr][i+2] + k2*v[dr][i+3];
            }
            ov[i >> 1] = __floats2half2_rn(lrelu(a0), lrelu(a1));
        }

        uint4* o16 = (uint4*)(dst + h*WW + seg);
        o16[0] = *(uint4*)&ov[0];
        o16[1] = *(uint4*)&ov[4];
    }
}

// ---------------------------------------------------------------------------
// GEMM: fp16 mma m16n8k16, 6-stage cp.async pipeline (KCH=16), XOR swizzles.
// Single __syncthreads per chunk (stage reuse distance proof: stage loaded at
// iter c was last read in chunk c-1; every warp passed this chunk's barrier
// only after finishing chunk c-1's compute).
// Block tile M=128 x N=128, 8 warps of 64x32. grid = (HH, B), block = 256.
// ---------------------------------------------------------------------------
__global__ void __launch_bounds__(256, 2)
gemm_f16(const float* __restrict__ bias,
         const float* __restrict__ x0,
         float* __restrict__ out)
{
    __shared__ __align__(16) __half sA[NSTAGE][C*KCH];     // 6 x 4096 B
    __shared__ __align__(16) __half sB[NSTAGE][KCH*128];   // 6 x 4096 B

    const int b    = blockIdx.y;
    const int h    = blockIdx.x;
    const int tid  = threadIdx.x;
    const int wid  = tid >> 5;
    const int lane = tid & 31;
    const int g    = lane >> 2;
    const int tg   = lane & 3;
    const int wm0  = (wid >> 2) * 64;
    const int wn0  = (wid & 3) * 32;

    float d[4][4][4];
    #pragma unroll
    for (int mt = 0; mt < 4; ++mt)
        #pragma unroll
        for (int nt = 0; nt < 4; ++nt)
            #pragma unroll
            for (int r = 0; r < 4; ++r) d[mt][nt][r] = 0.f;

    const __half* __restrict__ midb = g_midh + ((size_t)b*C)*HW + h*WW;

    const int sao = tid >> 1;              // 0..127 (o row)
    const int sau = tid & 1;               // A unit 0..1
    const int saus = sau ^ ((sao >> 2) & 1);
    const int sbk = tid >> 4;              // 0..15 (k row)
    const int sbu = tid & 15;              // B unit 0..15
    const int sbus = sbu ^ (sbk & 7);

#define LOAD_CHUNK(cc, st) do {                                                \
        cp16(&sA[st][sao*KCH + saus*8], g_wh + sao*C + (cc)*KCH + sau*8);      \
        cp16(&sB[st][sbk*128 + sbus*8],                                        \
             midb + (size_t)((cc)*KCH + sbk)*HW + sbu*8);                      \
        cp_commit();                                                           \
    } while (0)

    // prologue: 5 chunks ahead
    LOAD_CHUNK(0, 0);
    LOAD_CHUNK(1, 1);
    LOAD_CHUNK(2, 2);
    LOAD_CHUNK(3, 3);
    LOAD_CHUNK(4, 4);

    #pragma unroll
    for (int c = 0; c < NCHUNK; ++c) {
        const int st = c % NSTAGE;
        switch (NCHUNK - 1 - c) {
            case 0:  asm volatile("cp.async.wait_group 0;"); break;
            case 1:  asm volatile("cp.async.wait_group 1;"); break;
            case 2:  asm volatile("cp.async.wait_group 2;"); break;
            case 3:  asm volatile("cp.async.wait_group 3;"); break;
            default: asm volatile("cp.async.wait_group 4;"); break;
        }
        __syncthreads();

        uint32_t af[4][4];
        const int arow = lane & 15;
        const int au   = lane >> 4;
        #pragma unroll
        for (int mt = 0; mt < 4; ++mt) {
            const int r = wm0 + mt*16 + arow;
            ldmatrix_x4(af[mt], &sA[st][r*KCH + ((au ^ ((r >> 2) & 1)) << 3)]);
        }

        uint32_t bf[4][2];
        const int brow = lane & 15;
        #pragma unroll
        for (int nt = 0; nt < 4; ++nt) {
            const int un = (wn0 + nt*8) >> 3;
            ldmatrix_x2_t(bf[nt], &sB[st][brow*128 + ((un ^ (brow & 7)) << 3)]);
        }

        #pragma unroll
        for (int mt = 0; mt < 4; ++mt)
            #pragma unroll
            for (int nt = 0; nt < 4; ++nt)
                mma_f16(d[mt][nt], af[mt], bf[nt]);

        if (c + NSTAGE - 1 < NCHUNK)
            LOAD_CHUNK(c + NSTAGE - 1, (c + NSTAGE - 1) % NSTAGE);
    }

    // ---- fused epilogue: bias + x0*att residual (plain loads/stores) ----
    const int pix0 = h * WW;
    #pragma unroll
    for (int mt = 0; mt < 4; ++mt) {
        #pragma unroll
        for (int half = 0; half < 2; ++half) {
            const int o  = wm0 + mt*16 + g + half*8;
            const float bo = bias[o];
            const float at = g_att[b*C + o];
            const float* __restrict__ xrow = x0  + ((size_t)(b*C + o))*HW + pix0;
            float* __restrict__       orow = out + ((size_t)(b*C + o))*HW + pix0;
            #pragma unroll
            for (int nt = 0; nt < 4; ++nt) {
                const int cc2 = wn0 + nt*8 + 2*tg;
                float2 xv = *(const float2*)(xrow + cc2);
                float2 ov;
                ov.x = d[mt][nt][half*2 + 0] + bo + xv.x*at;
                ov.y = d[mt][nt][half*2 + 1] + bo + xv.y*at;
                *(float2*)(orow + cc2) = ov;
            }
        }
    }
}

// ---------------------------------------------------------------------------
extern "C" void kernel_launch(void* const* d_in, const int* in_sizes, int n_in,
                              void* d_out, int out_size)
{
    const float* x0    = (const float*)d_in[0];
    const float* deg   = (const float*)d_in[1];
    const float* w1    = (const float*)d_in[2];
    const float* w2    = (const float*)d_in[3];
    const float* convw = (const float*)d_in[4];
    const float* convb = (const float*)d_in[5];
    const float* caw1  = (const float*)d_in[6];
    const float* caw2  = (const float*)d_in[7];
    float* out = (float*)d_out;

    prep1_kernel<<<144, 256>>>(deg, w1, caw1);
    prep1b_kernel<<<B, 256>>>(caw2, convw);
    dwconv_kernel<<<B*C, 256>>>(x0, w2);
    gemm_f16<<<dim3(HH, B), 256>>>(convb, x0, out);
}

// round 15
// speedup vs baseline: 1.2103x; 1.2103x over previous
#include <cuda_runtime.h>
#include <cuda_fp16.h>
#include <math.h>
#include <stdint.h>

#define B    16
#define C    128
#define HH   128
#define WW   128
#define HW   (HH*WW)
#define KK   9
#define KCH  16
#define NCHUNK (C/KCH)     // 8
#define NSTAGE 6

// Scratch. g_midh layout: [b][c][h][w]
__device__ __half g_midh[(size_t)B*C*HW];
__device__ __half g_wh[C*C];               // conv weights fp16 [o][k]
__device__ float  g_att[B*C];              // CA attention
__device__ float  g_t[B*C];                // hidden MLP activations
__device__ float  g_hid[B*16];             // CA hidden activations

__device__ __forceinline__ float lrelu(float v) { return v > 0.f ? v : 0.1f*v; }

__device__ __forceinline__ void cp16(void* dst, const void* src) {
    uint32_t d = (uint32_t)__cvta_generic_to_shared(dst);
    asm volatile("cp.async.cg.shared.global [%0], [%1], 16;" :: "r"(d), "l"(src));
}
__device__ __forceinline__ void cp_commit() {
    asm volatile("cp.async.commit_group;");
}

__device__ __forceinline__ void ldmatrix_x4(uint32_t* r, const void* p) {
    uint32_t a = (uint32_t)__cvta_generic_to_shared(p);
    asm volatile("ldmatrix.sync.aligned.m8n8.x4.shared.b16 {%0,%1,%2,%3}, [%4];"
                 : "=r"(r[0]), "=r"(r[1]), "=r"(r[2]), "=r"(r[3]) : "r"(a));
}
__device__ __forceinline__ void ldmatrix_x2_t(uint32_t* r, const void* p) {
    uint32_t a = (uint32_t)__cvta_generic_to_shared(p);
    asm volatile("ldmatrix.sync.aligned.m8n8.x2.trans.shared.b16 {%0,%1}, [%2];"
                 : "=r"(r[0]), "=r"(r[1]) : "r"(a));
}
__device__ __forceinline__ void mma_f16(float* d, const uint32_t* a, const uint32_t* b) {
    asm volatile(
        "mma.sync.aligned.m16n8k16.row.col.f32.f16.f16.f32 "
        "{%0,%1,%2,%3}, {%4,%5,%6,%7}, {%8,%9}, {%0,%1,%2,%3};"
        : "+f"(d[0]), "+f"(d[1]), "+f"(d[2]), "+f"(d[3])
        : "r"(a[0]), "r"(a[1]), "r"(a[2]), "r"(a[3]), "r"(b[0]), "r"(b[1]));
}

// ---------------------------------------------------------------------------
// P1: one block per MLP output j (144 = 128 t-outputs + 16 CA-hidden).
// ---------------------------------------------------------------------------
__global__ void prep1_kernel(const float* __restrict__ deg,
                             const float* __restrict__ w1,
                             const float* __restrict__ caw1)
{
    const int j    = blockIdx.x;
    const int tid  = threadIdx.x;
    const int wid  = tid >> 5;
    const int lane = tid & 31;

    __shared__ float sdeg[B][C];

    #pragma unroll
    for (int i = tid; i < B*C; i += 256)
        ((float*)sdeg)[i] = deg[i];
    __syncthreads();

    const float* wrow = (j < 128) ? (w1 + j*C) : (caw1 + (j-128)*C);
    float w[4];
    #pragma unroll
    for (int u = 0; u < 4; ++u) w[u] = wrow[lane*4 + u];

    #pragma unroll
    for (int rep = 0; rep < 2; ++rep) {
        const int b = wid + rep*8;
        float acc = 0.f;
        #pragma unroll
        for (int u = 0; u < 4; ++u) acc += sdeg[b][lane*4 + u]*w[u];
        #pragma unroll
        for (int s = 16; s > 0; s >>= 1) acc += __shfl_xor_sync(0xffffffffu, acc, s);
        if (lane == 0) {
            if (j < 128) g_t[b*C + j]        = lrelu(acc);
            else         g_hid[b*16 + j-128] = lrelu(acc);
        }
    }
}

// ---------------------------------------------------------------------------
// P1b: CA attention sigmoid + fp16 weight conversion. grid = B, block = 256.
// ---------------------------------------------------------------------------
__global__ void prep1b_kernel(const float* __restrict__ caw2,
                              const float* __restrict__ convw)
{
    const int b   = blockIdx.x;
    const int tid = threadIdx.x;

    __shared__ float shid[16];
    if (tid < 16) shid[tid] = g_hid[b*16 + tid];
    __syncthreads();

    if (tid < C) {
        float acc = 0.f;
        const float* wrow = caw2 + tid*16;
        #pragma unroll
        for (int r = 0; r < 16; ++r) acc += shid[r]*wrow[r];
        g_att[b*C + tid] = 1.f/(1.f + expf(-acc));
    }

    {
        const int base = b*1024 + tid*4;
        float4 v = *(const float4*)(convw + base);
        g_wh[base+0] = __float2half(v.x);
        g_wh[base+1] = __float2half(v.y);
        g_wh[base+2] = __float2half(v.z);
        g_wh[base+3] = __float2half(v.w);
    }
}

// ---------------------------------------------------------------------------
// dwconv (+ fused coefficient dots): one block per (b,c) plane.
// Register row-rotation + warp shuffles: each warp owns a 16-row strip;
// lane l owns cols 4l..4l+3. Per step: 1 LDG.128 (new bottom row) + 2 SHFL
// (side halos from neighbor lanes) + 1 STG.64. Rows rotate in registers.
// grid = B*C, block = 256 (8 warps x 16 rows = 128 rows).
// ---------------------------------------------------------------------------
__global__ void dwconv_kernel(const float* __restrict__ x0,
                              const float* __restrict__ w2)
{
    const int bc   = blockIdx.x;
    const int b    = bc >> 7;
    const int c    = bc & 127;
    const int tid  = threadIdx.x;
    const int wid  = tid >> 5;
    const int lane = tid & 31;

    __shared__ float sk[9];
    __shared__ float st[C];

    if (tid < C) st[tid] = g_t[b*C + tid];
    __syncthreads();

    for (int j = wid; j < KK; j += 8) {
        const float* wrow = w2 + (size_t)(c*KK + j)*C;
        float acc = 0.f;
        #pragma unroll
        for (int u = 0; u < 4; ++u) {
            const int idx = lane*4 + u;
            acc += st[idx]*wrow[idx];
        }
        #pragma unroll
        for (int s = 16; s > 0; s >>= 1) acc += __shfl_xor_sync(0xffffffffu, acc, s);
        if (lane == 0) sk[j] = acc;
    }
    __syncthreads();

    float k[9];
    #pragma unroll
    for (int i = 0; i < 9; ++i) k[i] = sk[i];

    const float* __restrict__ src = x0 + (size_t)bc*HW;
    __half* __restrict__ dst = g_midh + (size_t)bc*HW;

    const int w0 = lane * 4;      // column strip
    const int hb = wid * 16;      // row strip base

    float4 vm, vc, vp;
    float  lm, rm, lc, rc, lp, rp;

    // row loader (hh is warp-uniform -> no divergence; shuffles are full-warp)
#define LOADROW(hh, v, l, r) do {                                              \
        if ((hh) < 0 || (hh) >= HH) {                                          \
            (v).x = (v).y = (v).z = (v).w = 0.f; (l) = 0.f; (r) = 0.f;         \
        } else {                                                               \
            (v) = *(const float4*)(src + (hh)*WW + w0);                        \
            float _lv = __shfl_up_sync(0xffffffffu, (v).w, 1);                 \
            float _rv = __shfl_down_sync(0xffffffffu, (v).x, 1);               \
            (l) = (lane == 0)  ? 0.f : _lv;                                    \
            (r) = (lane == 31) ? 0.f : _rv;                                    \
        }                                                                      \
    } while (0)

    LOADROW(hb - 1, vm, lm, rm);
    LOADROW(hb,     vc, lc, rc);

    #pragma unroll
    for (int s = 0; s < 16; ++s) {
        const int h = hb + s;
        LOADROW(h + 1, vp, lp, rp);

        float a0 = k[0]*lm   + k[1]*vm.x + k[2]*vm.y
                 + k[3]*lc   + k[4]*vc.x + k[5]*vc.y
                 + k[6]*lp   + k[7]*vp.x + k[8]*vp.y;
        float a1 = k[0]*vm.x + k[1]*vm.y + k[2]*vm.z
                 + k[3]*vc.x + k[4]*vc.y + k[5]*vc.z
                 + k[6]*vp.x + k[7]*vp.y + k[8]*vp.z;
        float a2 = k[0]*vm.y + k[1]*vm.z + k[2]*vm.w
                 + k[3]*vc.y + k[4]*vc.z + k[5]*vc.w
                 + k[6]*vp.y + k[7]*vp.z + k[8]*vp.w;
        float a3 = k[0]*vm.z + k[1]*vm.w + k[2]*rm
                 + k[3]*vc.z + k[4]*vc.w + k[5]*rc
                 + k[6]*vp.z + k[7]*vp.w + k[8]*rp;

        __half2 h01 = __floats2half2_rn(lrelu(a0), lrelu(a1));
        __half2 h23 = __floats2half2_rn(lrelu(a2), lrelu(a3));
        uint2 pk;
        pk.x = *(uint32_t*)&h01;
        pk.y = *(uint32_t*)&h23;
        *(uint2*)(dst + h*WW + w0) = pk;

        vm = vc; lm = lc; rm = rc;
        vc = vp; lc = lp; rc = rp;
    }
#undef LOADROW
}

// ---------------------------------------------------------------------------
// GEMM: fp16 mma m16n8k16, 6-stage cp.async pipeline (KCH=16), XOR swizzles.
// Identical to R14 (passing, 80 us).
// ---------------------------------------------------------------------------
__global__ void __launch_bounds__(256, 2)
gemm_f16(const float* __restrict__ bias,
         const float* __restrict__ x0,
         float* __restrict__ out)
{
    __shared__ __align__(16) __half sA[NSTAGE][C*KCH];     // 6 x 4096 B
    __shared__ __align__(16) __half sB[NSTAGE][KCH*128];   // 6 x 4096 B

    const int b    = blockIdx.y;
    const int h    = blockIdx.x;
    const int tid  = threadIdx.x;
    const int wid  = tid >> 5;
    const int lane = tid & 31;
    const int g    = lane >> 2;
    const int tg   = lane & 3;
    const int wm0  = (wid >> 2) * 64;
    const int wn0  = (wid & 3) * 32;

    float d[4][4][4];
    #pragma unroll
    for (int mt = 0; mt < 4; ++mt)
        #pragma unroll
        for (int nt = 0; nt < 4; ++nt)
            #pragma unroll
            for (int r = 0; r < 4; ++r) d[mt][nt][r] = 0.f;

    const __half* __restrict__ midb = g_midh + ((size_t)b*C)*HW + h*WW;

    const int sao = tid >> 1;
    const int sau = tid & 1;
    const int saus = sau ^ ((sao >> 2) & 1);
    const int sbk = tid >> 4;
    const int sbu = tid & 15;
    const int sbus = sbu ^ (sbk & 7);

#define LOAD_CHUNK(cc, st) do {                                                \
        cp16(&sA[st][sao*KCH + saus*8], g_wh + sao*C + (cc)*KCH + sau*8);      \
        cp16(&sB[st][sbk*128 + sbus*8],                                        \
             midb + (size_t)((cc)*KCH + sbk)*HW + sbu*8);                      \
        cp_commit();                                                           \
    } while (0)

    LOAD_CHUNK(0, 0);
    LOAD_CHUNK(1, 1);
    LOAD_CHUNK(2, 2);
    LOAD_CHUNK(3, 3);
    LOAD_CHUNK(4, 4);

    #pragma unroll
    for (int c = 0; c < NCHUNK; ++c) {
        const int st = c % NSTAGE;
        switch (NCHUNK - 1 - c) {
            case 0:  asm volatile("cp.async.wait_group 0;"); break;
            case 1:  asm volatile("cp.async.wait_group 1;"); break;
            case 2:  asm volatile("cp.async.wait_group 2;"); break;
            case 3:  asm volatile("cp.async.wait_group 3;"); break;
            default: asm volatile("cp.async.wait_group 4;"); break;
        }
        __syncthreads();

        uint32_t af[4][4];
        const int arow = lane & 15;
        const int au   = lane >> 4;
        #pragma unroll
        for (int mt = 0; mt < 4; ++mt) {
            const int r = wm0 + mt*16 + arow;
            ldmatrix_x4(af[mt], &sA[st][r*KCH + ((au ^ ((r >> 2) & 1)) << 3)]);
        }

        uint32_t bf[4][2];
        const int brow = lane & 15;
        #pragma unroll
        for (int nt = 0; nt < 4; ++nt) {
            const int un = (wn0 + nt*8) >> 3;
            ldmatrix_x2_t(bf[nt], &sB[st][brow*128 + ((un ^ (brow & 7)) << 3)]);
        }

        #pragma unroll
        for (int mt = 0; mt < 4; ++mt)
            #pragma unroll
            for (int nt = 0; nt < 4; ++nt)
                mma_f16(d[mt][nt], af[mt], bf[nt]);

        if (c + NSTAGE - 1 < NCHUNK)
            LOAD_CHUNK(c + NSTAGE - 1, (c + NSTAGE - 1) % NSTAGE);
    }

    // ---- fused epilogue: bias + x0*att residual (plain loads/stores) ----
    const int pix0 = h * WW;
    #pragma unroll
    for (int mt = 0; mt < 4; ++mt) {
        #pragma unroll
        for (int half = 0; half < 2; ++half) {
            const int o  = wm0 + mt*16 + g + half*8;
            const float bo = bias[o];
            const float at = g_att[b*C + o];
            const float* __restrict__ xrow = x0  + ((size_t)(b*C + o))*HW + pix0;
            float* __restrict__       orow = out + ((size_t)(b*C + o))*HW + pix0;
            #pragma unroll
            for (int nt = 0; nt < 4; ++nt) {
                const int cc2 = wn0 + nt*8 + 2*tg;
                float2 xv = *(const float2*)(xrow + cc2);
                float2 ov;
                ov.x = d[mt][nt][half*2 + 0] + bo + xv.x*at;
                ov.y = d[mt][nt][half*2 + 1] + bo + xv.y*at;
                *(float2*)(orow + cc2) = ov;
            }
        }
    }
}

// ---------------------------------------------------------------------------
extern "C" void kernel_launch(void* const* d_in, const int* in_sizes, int n_in,
                              void* d_out, int out_size)
{
    const float* x0    = (const float*)d_in[0];
    const float* deg   = (const float*)d_in[1];
    const float* w1    = (const float*)d_in[2];
    const float* w2    = (const float*)d_in[3];
    const float* convw = (const float*)d_in[4];
    const float* convb = (const float*)d_in[5];
    const float* caw1  = (const float*)d_in[6];
    const float* caw2  = (const float*)d_in[7];
    float* out = (float*)d_out;

    prep1_kernel<<<144, 256>>>(deg, w1, caw1);
    prep1b_kernel<<<B, 256>>>(caw2, convw);
    dwconv_kernel<<<B*C, 256>>>(x0, w2);
    gemm_f16<<<dim3(HH, B), 256>>>(convb, x0, out);
}